// round 8
// baseline (speedup 1.0000x reference)
#include <cuda_runtime.h>
#include <cuda_bf16.h>
#include <math_constants.h>

// RoI max pooling (Caffe-style), bit-matching the JAX/XLA:CPU reference.
// VERIFIED ARITHMETIC (R6, rel_err==0.0) — do not alter:
//   rs* = rintf(__fmul_rn(coord, scale))
//   bh  = __fmul_rn(roi_h, 1.0f/7.0f)      (XLA fast-math reciprocal form)
//   hstart = floorf(__fmul_rn(ph, bh)) + rsh ; hend = ceilf(__fmul_rn(ph+1, bh)) + rsh
//   clip to [0,64]; empty bin -> 0.
//
// Three-kernel pipeline (all in one graph):
//   setup : per-roi geometry tables (1 block)
//   phase1: rowmax[n,c,ph,w] — coalesced row loads, vertical max per h-bin
//   phase2: out[n,c,ph,pw]   — horizontal max over rowmax window

#define CROP_H 7
#define CROP_W 7
#define NROI   128
#define BMAX   4
#define HH     64
#define WW     64
#define CC     256

__device__ int   g_hs[NROI * CROP_H];
__device__ int   g_he[NROI * CROP_H];
__device__ int   g_ws[NROI * CROP_W];
__device__ int   g_we[NROI * CROP_W];
__device__ int   g_wlo[NROI];
__device__ int   g_whi[NROI];
__device__ int   g_base[NROI];                      // batch*C*H*W
__device__ float g_scratch[NROI * CC * CROP_H * WW]; // rowmax, ~59 MB

__global__ void setup_kernel(const float* __restrict__ rois,
                             const int*   __restrict__ roibatches,
                             const float* __restrict__ scale_ptr)
{
    int n = threadIdx.x;
    if (n >= NROI) return;

    float scale = scale_ptr[0];
    float x1 = rois[n * 4 + 0];
    float y1 = rois[n * 4 + 1];
    float x2 = rois[n * 4 + 2];
    float y2 = rois[n * 4 + 3];

    int rsw = (int)rintf(__fmul_rn(x1, scale));
    int rsh = (int)rintf(__fmul_rn(y1, scale));
    int rew = (int)rintf(__fmul_rn(x2, scale));
    int reh = (int)rintf(__fmul_rn(y2, scale));

    float roi_h = (float)max(reh - rsh + 1, 1);
    float roi_w = (float)max(rew - rsw + 1, 1);
    const float RCP7 = 1.0f / 7.0f;
    float bh = __fmul_rn(roi_h, RCP7);
    float bw = __fmul_rn(roi_w, RCP7);

    #pragma unroll
    for (int p = 0; p < CROP_H; ++p) {
        int hs = (int)floorf(__fmul_rn((float)p, bh)) + rsh;
        int he = (int)ceilf (__fmul_rn((float)p + 1.0f, bh)) + rsh;
        g_hs[n * CROP_H + p] = min(max(hs, 0), HH);
        g_he[n * CROP_H + p] = min(max(he, 0), HH);

        int ws = (int)floorf(__fmul_rn((float)p, bw)) + rsw;
        int we = (int)ceilf (__fmul_rn((float)p + 1.0f, bw)) + rsw;
        g_ws[n * CROP_W + p] = min(max(ws, 0), WW);
        g_we[n * CROP_W + p] = min(max(we, 0), WW);
    }
    g_wlo[n]  = min(max(rsw, 0), WW);
    g_whi[n]  = min(max((int)ceilf(__fmul_rn(7.0f, bw)) + rsw, 0), WW);
    g_base[n] = roibatches[n] * CC * HH * WW;
}

// thread = (((pair)*7 + ph)*64 + w), pair = n*C + c, w fastest (coalesced)
__global__ __launch_bounds__(256)
void phase1_kernel(const float* __restrict__ data, int total)
{
    int tid = blockIdx.x * blockDim.x + threadIdx.x;
    if (tid >= total) return;

    int w    = tid & (WW - 1);
    int r    = tid >> 6;            // pair*7 + ph
    int pair = r / CROP_H;
    int ph   = r - pair * CROP_H;
    int n    = pair >> 8;           // / CC
    int c    = pair & (CC - 1);

    if (w < g_wlo[n] || w >= g_whi[n]) return;

    int hs = g_hs[n * CROP_H + ph];
    int he = g_he[n * CROP_H + ph];

    const float* p = data + g_base[n] + c * (HH * WW) + w;
    float m = -CUDART_INF_F;
    for (int h = hs; h < he; ++h)
        m = fmaxf(m, __ldg(p + h * WW));

    g_scratch[r * WW + w] = m;
}

// thread = output element idx = ((pair)*7 + ph)*7 + pw
__global__ __launch_bounds__(256)
void phase2_kernel(float* __restrict__ out, int total)
{
    int idx = blockIdx.x * blockDim.x + threadIdx.x;
    if (idx >= total) return;

    int pw   = idx % CROP_W;
    int t    = idx / CROP_W;
    int ph   = t % CROP_H;
    int pair = t / CROP_H;
    int n    = pair >> 8;

    int hs = g_hs[n * CROP_H + ph];
    int he = g_he[n * CROP_H + ph];
    int ws = g_ws[n * CROP_W + pw];
    int we = g_we[n * CROP_W + pw];

    if (he <= hs || we <= ws) { out[idx] = 0.0f; return; }

    const float* rm = &g_scratch[(size_t)t * WW];
    float m = -CUDART_INF_F;
    for (int w = ws; w < we; ++w)
        m = fmaxf(m, rm[w]);

    out[idx] = m;
}

extern "C" void kernel_launch(void* const* d_in, const int* in_sizes, int n_in,
                              void* d_out, int out_size)
{
    const float* data      = nullptr;
    const float* rois      = nullptr;
    const int*   batches   = nullptr;
    const float* scale_ptr = nullptr;

    for (int i = 0; i < n_in; ++i) {
        int sz = in_sizes[i];
        if (sz == 1)            scale_ptr = (const float*)d_in[i];
        else if (sz == 128)     batches   = (const int*)d_in[i];
        else if (sz == 512)     rois      = (const float*)d_in[i];
        else                    data      = (const float*)d_in[i];
    }

    float* out = (float*)d_out;

    setup_kernel<<<1, 128>>>(rois, batches, scale_ptr);

    int p1_total = NROI * CC * CROP_H * WW;         // 14,680,064
    phase1_kernel<<<(p1_total + 255) / 256, 256>>>(data, p1_total);

    int p2_total = out_size;                        // 1,605,632
    phase2_kernel<<<(p2_total + 255) / 256, 256>>>(out, p2_total);
}

// round 9
// speedup vs baseline: 1.3922x; 1.3922x over previous
#include <cuda_runtime.h>
#include <cuda_bf16.h>
#include <math_constants.h>

// RoI max pooling (Caffe-style), bit-matching the JAX/XLA:CPU reference.
// VERIFIED ARITHMETIC (R6, rel_err==0.0) — do not alter:
//   rs*    = rintf(__fmul_rn(coord, scale))
//   bh/bw  = __fmul_rn(roi_extent, 1.0f/7.0f)   (XLA fast-math reciprocal form)
//   hstart = floorf(__fmul_rn(ph, bh)) + rsh ; hend = ceilf(__fmul_rn(ph+1,bh)) + rsh
//   clip to [0,64]; empty bin (hend<=hstart || wend<=wstart) -> 0.
//
// Single fused kernel. Block = 512 threads: tx_w in [0,64) x c_local in [0,8).
// Grid = (roi n: 128) x (channel tile: 32).  Per ph bin:
//   - each thread vertical-maxes one column w = wlo + tx_w over the bin rows
//     (bounds UNIFORM per block -> no divergence; consecutive lanes -> fully
//     coalesced, 1 L1 wavefront per row per channel)
//   - rowmax -> smem, then 56 threads (8c x 7pw) reduce horizontal windows.

#define CROP_H 7
#define CROP_W 7
#define NROI   128
#define HH     64
#define WW     64
#define CC     256
#define CLOC   8          // channels per block
#define CTILES (CC / CLOC)

__global__ __launch_bounds__(512)
void roipool_fused_kernel(const float* __restrict__ data,
                          const float* __restrict__ rois,
                          const int*   __restrict__ roibatches,
                          const float* __restrict__ scale_ptr,
                          float* __restrict__ out)
{
    __shared__ float rm[CLOC][WW];

    int n    = blockIdx.x >> 5;          // / CTILES
    int tile = blockIdx.x & (CTILES - 1);
    int tx_w    = threadIdx.x & (WW - 1);
    int c_local = threadIdx.x >> 6;
    int c       = tile * CLOC + c_local;

    // ---- per-roi geometry (uniform across block, verified arithmetic) ----
    float scale = __ldg(scale_ptr);
    float x1 = __ldg(&rois[n * 4 + 0]);
    float y1 = __ldg(&rois[n * 4 + 1]);
    float x2 = __ldg(&rois[n * 4 + 2]);
    float y2 = __ldg(&rois[n * 4 + 3]);

    int rsw = (int)rintf(__fmul_rn(x1, scale));
    int rsh = (int)rintf(__fmul_rn(y1, scale));
    int rew = (int)rintf(__fmul_rn(x2, scale));
    int reh = (int)rintf(__fmul_rn(y2, scale));

    float roi_h = (float)max(reh - rsh + 1, 1);
    float roi_w = (float)max(rew - rsw + 1, 1);
    const float RCP7 = 1.0f / 7.0f;
    float bh = __fmul_rn(roi_h, RCP7);
    float bw = __fmul_rn(roi_w, RCP7);

    int wlo = min(max(rsw, 0), WW);
    int whi = min(max((int)ceilf(__fmul_rn(7.0f, bw)) + rsw, 0), WW);

    int b = __ldg(&roibatches[n]);
    const float* plane = data + ((size_t)b * CC + c) * (HH * WW);

    // reduce-role decomposition (threads 0..55)
    int r_c  = threadIdx.x / CROP_W;     // c_local for reduce
    int r_pw = threadIdx.x - r_c * CROP_W;
    bool is_reducer = threadIdx.x < CLOC * CROP_W;

    int my_w = wlo + tx_w;               // column this thread owns (if < whi)
    bool w_live = my_w < whi;

    #pragma unroll
    for (int ph = 0; ph < CROP_H; ++ph) {
        int hs = (int)floorf(__fmul_rn((float)ph, bh)) + rsh;
        int he = (int)ceilf (__fmul_rn((float)ph + 1.0f, bh)) + rsh;
        hs = min(max(hs, 0), HH);
        he = min(max(he, 0), HH);

        if (w_live) {
            float m = -CUDART_INF_F;
            const float* p = plane + my_w;
            for (int h = hs; h < he; ++h)
                m = fmaxf(m, __ldg(p + h * WW));
            rm[c_local][my_w] = m;
        }
        __syncthreads();

        if (is_reducer) {
            int ws = (int)floorf(__fmul_rn((float)r_pw, bw)) + rsw;
            int we = (int)ceilf (__fmul_rn((float)r_pw + 1.0f, bw)) + rsw;
            ws = min(max(ws, 0), WW);
            we = min(max(we, 0), WW);

            float m;
            if (he <= hs || we <= ws) {
                m = 0.0f;
            } else {
                m = -CUDART_INF_F;
                for (int w = ws; w < we; ++w)
                    m = fmaxf(m, rm[r_c][w]);
            }
            int cc = tile * CLOC + r_c;
            out[(((size_t)n * CC + cc) * CROP_H + ph) * CROP_W + r_pw] = m;
        }
        __syncthreads();
    }
}

extern "C" void kernel_launch(void* const* d_in, const int* in_sizes, int n_in,
                              void* d_out, int out_size)
{
    const float* data      = nullptr;
    const float* rois      = nullptr;
    const int*   batches   = nullptr;
    const float* scale_ptr = nullptr;

    for (int i = 0; i < n_in; ++i) {
        int sz = in_sizes[i];
        if (sz == 1)            scale_ptr = (const float*)d_in[i];
        else if (sz == 128)     batches   = (const int*)d_in[i];
        else if (sz == 512)     rois      = (const float*)d_in[i];
        else                    data      = (const float*)d_in[i];
    }

    float* out = (float*)d_out;

    int blocks = NROI * CTILES;   // 128 * 32 = 4096
    roipool_fused_kernel<<<blocks, 512>>>(data, rois, batches, scale_ptr, out);
}